// round 11
// baseline (speedup 1.0000x reference)
#include <cuda_runtime.h>
#include <cuda_bf16.h>

#define B 8
#define C 256
#define HW 2304
#define DK 32
#define C2 512

#define NP1   128                    // wide t-partial blocks (16 per batch)
#define NP2   8                      // per-batch combine blocks
#define NATTN 576                    // 72 tiles x 8 batches
#define NBLK  (NP1 + NP2 + NATTN)    // 712

// Scratch (device globals — zero-initialized; counters reset each launch)
__device__ float g_tp[8 * B * C2];   // p1 partials: [ct][b][j]
__device__ float g_vg[B * C];
__device__ float g_wqk[B * C];
__device__ float g_qb[B];
__device__ unsigned int g_cnt1[B];   // per-batch p1-done counters
__device__ unsigned int g_flag2[B];  // per-batch combine-done flags
__device__ unsigned int g_done;      // attn-done counter

__device__ __forceinline__ float ex2f(float x) {
    float y;
    asm("ex2.approx.ftz.f32 %0, %1;" : "=f"(y) : "f"(x));
    return y;
}

__device__ __forceinline__ float warp_sum(float v) {
    #pragma unroll
    for (int o = 16; o; o >>= 1) v += __shfl_xor_sync(0xffffffffu, v, o);
    return v;
}

__device__ __forceinline__ unsigned int ld_acquire_gpu(unsigned int* p) {
    unsigned int v;
    asm volatile("ld.acquire.gpu.u32 %0, [%1];" : "=r"(v) : "l"(p) : "memory");
    return v;
}

__device__ __forceinline__ void prefetch_l2(const void* p) {
    asm volatile("prefetch.global.L2 [%0];" :: "l"(p));
}

// packed f32x2 helpers
__device__ __forceinline__ unsigned long long pack2(float lo, float hi) {
    unsigned long long r;
    asm("mov.b64 %0, {%1, %2};" : "=l"(r) : "f"(lo), "f"(hi));
    return r;
}
__device__ __forceinline__ void unpack2(unsigned long long v, float& lo, float& hi) {
    asm("mov.b64 {%0, %1}, %2;" : "=f"(lo), "=f"(hi) : "l"(v));
}
__device__ __forceinline__ unsigned long long fma2(unsigned long long a,
                                                   unsigned long long b,
                                                   unsigned long long c) {
    unsigned long long d;
    asm("fma.rn.f32x2 %0, %1, %2, %3;" : "=l"(d) : "l"(a), "l"(b), "l"(c));
    return d;
}
__device__ __forceinline__ unsigned long long add2(unsigned long long a,
                                                   unsigned long long b) {
    unsigned long long d;
    asm("add.rn.f32x2 %0, %1, %2;" : "=l"(d) : "l"(a), "l"(b));
    return d;
}

// ---------------------------------------------------------------------------
// Stage 1: wide t-partials. blk = 0..127 (16 per batch).
// ---------------------------------------------------------------------------
__device__ void p1_block(int blk, int tid,
                         const float* __restrict__ text,
                         const float* __restrict__ Wg1)
{
    const int b  = blk >> 4;
    const int jh = (blk >> 3) & 1;
    const int ct = blk & 7;
    const int j  = jh * 256 + tid;

    __shared__ float text_s[32];
    if (tid < 32) text_s[tid] = text[b * C + ct * 32 + tid];
    __syncthreads();

    float acc = 0.0f;
    #pragma unroll
    for (int cc = 0; cc < 32; cc++) {
        acc = fmaf(text_s[cc], Wg1[(ct * 32 + cc) * C2 + j], acc);
    }
    g_tp[ct * (B * C2) + b * C2 + j] = acc;

    __syncthreads();
    if (tid == 0) {
        __threadfence();
        atomicAdd(&g_cnt1[b], 1u);
    }
}

// ---------------------------------------------------------------------------
// Stage 2: per-batch combine (256 threads). L2-prefetches its weights during
// the spin so the post-release load chain hits L2, not DRAM.
// ---------------------------------------------------------------------------
__device__ void p2_block(int b, int tid,
                         const float* __restrict__ bg1,
                         const float* __restrict__ ln_g, const float* __restrict__ ln_b,
                         const float* __restrict__ Wg2,  const float* __restrict__ bg2,
                         const float* __restrict__ Wq,   const float* __restrict__ bq,
                         const float* __restrict__ Wk,   const float* __restrict__ Wv)
{
    const int lane = tid & 31, wid = tid >> 5;   // 8 warps

    __shared__ float t_s[C2];
    __shared__ float gv_s[C];
    __shared__ float part_f[4 * 256];
    __shared__ float kg_s[DK];
    __shared__ float red[8];
    __shared__ float bcast[2];

    // ---- prefetch weights to L2 (fire-and-forget, before the spin) ----
    {
        const char* base2 = (const char*)Wg2;    // 512 KB -> 4096 lines
        #pragma unroll 4
        for (int i = tid; i < 4096; i += 256) prefetch_l2(base2 + i * 128);
        const char* basev = (const char*)Wv;     // 256 KB -> 2048 lines
        #pragma unroll 4
        for (int i = tid; i < 2048; i += 256) prefetch_l2(basev + i * 128);
        const char* baseq = (const char*)Wq;     // 32 KB -> 256 lines
        if (tid < 256) prefetch_l2(baseq + tid * 128);
        const char* basek = (const char*)Wk;     // 32 KB -> 256 lines
        prefetch_l2(basek + tid * 128);
    }

    // ---- wait for this batch's 16 p1 blocks ----
    if (tid == 0) {
        while (ld_acquire_gpu(&g_cnt1[b]) < 16u) __nanosleep(32);
    }
    __syncthreads();
    __threadfence();

    // ---- combine partials + bias (each thread: 2 j's) ----
    {
        float v0 = bg1[tid], v1 = bg1[tid + 256];
        #pragma unroll
        for (int ct = 0; ct < 8; ct++) {
            v0 += g_tp[ct * (B * C2) + b * C2 + tid];
            v1 += g_tp[ct * (B * C2) + b * C2 + tid + 256];
        }
        t_s[tid] = v0;
        t_s[tid + 256] = v1;
    }
    __syncthreads();

    // ---- LayerNorm + exact GELU ----
    const float v0 = t_s[tid], v1 = t_s[tid + 256];
    float s1 = warp_sum(v0 + v1);
    if (lane == 0) red[wid] = s1;
    __syncthreads();
    if (wid == 0) {
        float r = (lane < 8) ? red[lane] : 0.0f;
        r = warp_sum(r);
        if (lane == 0) bcast[0] = r * (1.0f / C2);
    }
    __syncthreads();
    const float mu = bcast[0];
    const float d0 = v0 - mu, d1 = v1 - mu;
    float s2 = warp_sum(d0 * d0 + d1 * d1);
    if (lane == 0) red[wid] = s2;
    __syncthreads();
    if (wid == 0) {
        float r = (lane < 8) ? red[lane] : 0.0f;
        r = warp_sum(r);
        if (lane == 0) bcast[1] = rsqrtf(r * (1.0f / C2) + 1e-5f);
    }
    __syncthreads();
    {
        const float rstd = bcast[1];
        float x0 = d0 * rstd * ln_g[tid] + ln_b[tid];
        float x1 = d1 * rstd * ln_g[tid + 256] + ln_b[tid + 256];
        t_s[tid]       = 0.5f * x0 * (1.0f + erff(x0 * 0.7071067811865476f));
        t_s[tid + 256] = 0.5f * x1 * (1.0f + erff(x1 * 0.7071067811865476f));
    }
    __syncthreads();

    // ---- GvT[c] = sum_k t[k] * Wg2[k*C+c] + bg2[c] (L2-hot) ----
    {
        const int q = tid & 63;
        const int h = tid >> 6;
        const float4* W4 = (const float4*)Wg2;   // [512][64] float4
        float4 a0 = make_float4(0,0,0,0), a1 = a0, a2 = a0, a3 = a0;
        const int k0 = h * 128;
        #pragma unroll 32
        for (int kk = 0; kk < 32; kk++) {
            const float t0 = t_s[k0 + kk];
            const float t1 = t_s[k0 + 32 + kk];
            const float t2 = t_s[k0 + 64 + kk];
            const float t3 = t_s[k0 + 96 + kk];
            const float4 w0 = W4[(k0 + kk) * 64 + q];
            const float4 w1 = W4[(k0 + 32 + kk) * 64 + q];
            const float4 w2 = W4[(k0 + 64 + kk) * 64 + q];
            const float4 w3 = W4[(k0 + 96 + kk) * 64 + q];
            a0.x = fmaf(t0, w0.x, a0.x); a0.y = fmaf(t0, w0.y, a0.y);
            a0.z = fmaf(t0, w0.z, a0.z); a0.w = fmaf(t0, w0.w, a0.w);
            a1.x = fmaf(t1, w1.x, a1.x); a1.y = fmaf(t1, w1.y, a1.y);
            a1.z = fmaf(t1, w1.z, a1.z); a1.w = fmaf(t1, w1.w, a1.w);
            a2.x = fmaf(t2, w2.x, a2.x); a2.y = fmaf(t2, w2.y, a2.y);
            a2.z = fmaf(t2, w2.z, a2.z); a2.w = fmaf(t2, w2.w, a2.w);
            a3.x = fmaf(t3, w3.x, a3.x); a3.y = fmaf(t3, w3.y, a3.y);
            a3.z = fmaf(t3, w3.z, a3.z); a3.w = fmaf(t3, w3.w, a3.w);
        }
        part_f[h * 256 + 4 * q + 0] = a0.x + a1.x + a2.x + a3.x;
        part_f[h * 256 + 4 * q + 1] = a0.y + a1.y + a2.y + a3.y;
        part_f[h * 256 + 4 * q + 2] = a0.z + a1.z + a2.z + a3.z;
        part_f[h * 256 + 4 * q + 3] = a0.w + a1.w + a2.w + a3.w;
    }
    __syncthreads();
    {
        float g = bg2[tid];
        #pragma unroll
        for (int h = 0; h < 4; h++) g += part_f[h * 256 + tid];
        gv_s[tid] = g;
    }
    __syncthreads();

    // ---- vg (32 outputs/warp) and kg (4 outputs/warp) ----
    {
        const float4* Wv4 = (const float4*)Wv;        // [256][64] float4
        const float4* gv4 = (const float4*)gv_s;
        const float4 gA = gv4[lane];
        const float4 gB = gv4[32 + lane];
        #pragma unroll 8
        for (int oo = 0; oo < 32; oo++) {
            const int c = wid * 32 + oo;
            const float4 wA = Wv4[c * 64 + lane];
            const float4 wB = Wv4[c * 64 + 32 + lane];
            float p = wA.x * gA.x + wA.y * gA.y + wA.z * gA.z + wA.w * gA.w
                    + wB.x * gB.x + wB.y * gB.y + wB.z * gB.z + wB.w * gB.w;
            p = warp_sum(p);
            if (lane == 0) g_vg[b * C + c] = p;
        }
        const float4* Wk4 = (const float4*)Wk;        // [32][64] float4
        #pragma unroll
        for (int oo = 0; oo < 4; oo++) {
            const int dd = wid * 4 + oo;
            const float4 wA = Wk4[dd * 64 + lane];
            const float4 wB = Wk4[dd * 64 + 32 + lane];
            float p = wA.x * gA.x + wA.y * gA.y + wA.z * gA.z + wA.w * gA.w
                    + wB.x * gB.x + wB.y * gB.y + wB.z * gB.z + wB.w * gB.w;
            p = warp_sum(p);
            if (lane == 0) kg_s[dd] = p;
        }
    }
    __syncthreads();

    // ---- wqk[c] = sum_d kg[d] * Wq[d*C+c]; qb = bq . kg ----
    {
        float acc = 0.0f;
        #pragma unroll
        for (int dd = 0; dd < DK; dd++) acc = fmaf(kg_s[dd], Wq[dd * C + tid], acc);
        g_wqk[b * C + tid] = acc;
    }
    if (wid == 0) {
        float p = bq[lane] * kg_s[lane];
        p = warp_sum(p);
        if (lane == 0) g_qb[b] = p;
    }

    __syncthreads();
    if (tid == 0) {
        __threadfence();
        atomicAdd(&g_flag2[b], 1u);
    }
}

// ---------------------------------------------------------------------------
// Fused kernel: 712 blocks x 256 threads.
// 0..127 p1 | 128..135 combine | 136..711 attn (per-batch gated).
// ---------------------------------------------------------------------------
__global__ __launch_bounds__(256, 4)
void fused_kernel(const float* __restrict__ img,
                  const float* __restrict__ text,
                  const float* __restrict__ l,
                  const float* __restrict__ Wg1, const float* __restrict__ bg1,
                  const float* __restrict__ ln_g, const float* __restrict__ ln_b,
                  const float* __restrict__ Wg2, const float* __restrict__ bg2,
                  const float* __restrict__ Wq,  const float* __restrict__ bq,
                  const float* __restrict__ Wk,  const float* __restrict__ Wv,
                  const float* __restrict__ bv,
                  const float* __restrict__ gamma_p,
                  float* __restrict__ out)
{
    const int tid = threadIdx.x;

    if (blockIdx.x < NP1) {
        p1_block(blockIdx.x, tid, text, Wg1);
        return;
    }
    if (blockIdx.x < NP1 + NP2) {
        p2_block(blockIdx.x - NP1, tid, bg1, ln_g, ln_b,
                 Wg2, bg2, Wq, bq, Wk, Wv);
        return;
    }

    // ---------------- attn block ----------------
    const int idx = blockIdx.x - (NP1 + NP2);   // 0..575
    const int bx = idx % 72;
    const int b  = idx / 72;
    const int p = tid & 31;      // pixel within block (lane)
    const int s = tid >> 5;      // split 0..7 (warp)
    const int i = bx * 32 + p;
    const int c0 = s * 32;

    __shared__ float2 ls2[HW / 2];
    __shared__ float wq[C];
    __shared__ float vgs[C];
    __shared__ float bvs[C];
    __shared__ float partA[256];
    __shared__ float partS[256];
    __shared__ float partT[256];
    __shared__ float rmx[8], rmn[8];

    // ---- pre-wait phase: independent of producers ----
    float im[32];
    const float* xb = img + (size_t)b * C * HW + (size_t)c0 * HW + i;
    #pragma unroll
    for (int cc = 0; cc < 32; cc++) im[cc] = xb[(size_t)cc * HW];

    // l -> smem, tracking local min/max (no producer dependency)
    float mx = -1e30f, mn = 1e30f;
    {
        float* lsf = (float*)ls2;
        #pragma unroll
        for (int j = tid; j < HW; j += 256) {
            const float v = l[j];
            lsf[j] = v;
            mx = fmaxf(mx, v);
            mn = fminf(mn, v);
        }
    }
    bvs[tid] = bv[tid];
    const float gm = *gamma_p;

    #pragma unroll
    for (int o = 16; o; o >>= 1) {
        mx = fmaxf(mx, __shfl_xor_sync(0xffffffffu, mx, o));
        mn = fminf(mn, __shfl_xor_sync(0xffffffffu, mn, o));
    }
    if (p == 0) { rmx[s] = mx; rmn[s] = mn; }
    __syncthreads();
    float lmax = rmx[0], lmin = rmn[0];
    #pragma unroll
    for (int k = 1; k < 8; k++) {
        lmax = fmaxf(lmax, rmx[k]);
        lmin = fminf(lmin, rmn[k]);
    }

    // ---- wait for THIS batch's combine only ----
    if (tid == 0) {
        while (ld_acquire_gpu(&g_flag2[b]) == 0u) __nanosleep(32);
    }
    __syncthreads();
    __threadfence();

    const float qb = g_qb[b];
    wq[tid]  = g_wqk[b * C + tid];
    vgs[tid] = g_vg[b * C + tid];
    __syncthreads();

    // partial dot over this thread's 32 channels
    float a = 0.0f;
    #pragma unroll
    for (int cc = 0; cc < 32; cc++) a = fmaf(wq[c0 + cc], im[cc], a);
    partA[tid] = a;
    __syncthreads();
    float af = qb;
    #pragma unroll
    for (int k = 0; k < 8; k++) af += partA[k * 32 + p];

    // softmax-weighted sum of l (rank-1 logits), exp2 domain, f32x2-packed
    const float al = af * 1.4426950408889634f;
    const float m2 = (al > 0.0f) ? al * lmax : al * lmin;
    const unsigned long long al2  = pack2(al, al);
    const unsigned long long m2n2 = pack2(-m2, -m2);
    unsigned long long S2 = pack2(0.0f, 0.0f);
    unsigned long long T2 = S2;
    const int base2 = s * (HW / 16);
    #pragma unroll 8
    for (int jj = 0; jj < HW / 16; jj++) {
        const float2 lj2f = ls2[base2 + jj];
        const unsigned long long lj2 = pack2(lj2f.x, lj2f.y);
        const unsigned long long u2 = fma2(al2, lj2, m2n2);
        float u0, u1;
        unpack2(u2, u0, u1);
        const unsigned long long e2 = pack2(ex2f(u0), ex2f(u1));
        S2 = add2(S2, e2);
        T2 = fma2(lj2, e2, T2);
    }
    float S0, S1, T0, T1;
    unpack2(S2, S0, S1);
    unpack2(T2, T0, T1);
    partS[tid] = S0 + S1;
    partT[tid] = T0 + T1;
    __syncthreads();
    float Ss = 0.0f, Ts = 0.0f;
    #pragma unroll
    for (int k = 0; k < 8; k++) {
        Ss += partS[k * 32 + p];
        Ts += partT[k * 32 + p];
    }
    const float sv = Ts / Ss;

    // out = img + gamma * (vg*sv + bv), register-cached img
    float* ob = out + (size_t)b * C * HW + (size_t)c0 * HW + i;
    #pragma unroll
    for (int cc = 0; cc < 32; cc++) {
        ob[(size_t)cc * HW] = fmaf(gm, fmaf(vgs[c0 + cc], sv, bvs[c0 + cc]), im[cc]);
    }

    // ---- reset counters for next launch (graph replay safe) ----
    if (tid == 0) {
        const unsigned int old = atomicAdd(&g_done, 1u);
        if (old == NATTN - 1) {
            #pragma unroll
            for (int k = 0; k < B; k++) { g_cnt1[k] = 0; g_flag2[k] = 0; }
            g_done = 0;
        }
    }
}

extern "C" void kernel_launch(void* const* d_in, const int* in_sizes, int n_in,
                              void* d_out, int out_size)
{
    const float* img   = (const float*)d_in[0];
    const float* text  = (const float*)d_in[1];
    const float* l     = (const float*)d_in[2];
    const float* Wg1   = (const float*)d_in[3];
    const float* bg1   = (const float*)d_in[4];
    const float* ln_g  = (const float*)d_in[5];
    const float* ln_b  = (const float*)d_in[6];
    const float* Wg2   = (const float*)d_in[7];
    const float* bg2   = (const float*)d_in[8];
    const float* Wq    = (const float*)d_in[9];
    const float* bq    = (const float*)d_in[10];
    const float* Wk    = (const float*)d_in[11];
    // d_in[12] = bk : cancels in softmax, unused
    const float* Wv    = (const float*)d_in[13];
    const float* bv    = (const float*)d_in[14];
    const float* gamma = (const float*)d_in[15];
    float* out = (float*)d_out;

    fused_kernel<<<NBLK, 256>>>(img, text, l, Wg1, bg1, ln_g, ln_b,
                                Wg2, bg2, Wq, bq, Wk, Wv, bv, gamma, out);
}

// round 12
// speedup vs baseline: 1.2742x; 1.2742x over previous
#include <cuda_runtime.h>
#include <cuda_bf16.h>

#define B 8
#define C 256
#define HW 2304
#define DK 32
#define C2 512

// Scratch (device globals — no allocation allowed)
__device__ float g_tp[8 * B * C2]; // p1 partials: [ct][b][j]
__device__ float g_vg[B * C];      // vg = Wv @ GvT
__device__ float g_wqk[B * C];     // wqk = kg @ Wq
__device__ float g_qb[B];          // qb = bq . kg
__device__ float g_lmax, g_lmin;   // reduced once from l

__device__ __forceinline__ float ex2f(float x) {
    float y;
    asm("ex2.approx.ftz.f32 %0, %1;" : "=f"(y) : "f"(x));
    return y;
}

__device__ __forceinline__ float warp_sum(float v) {
    #pragma unroll
    for (int o = 16; o; o >>= 1) v += __shfl_xor_sync(0xffffffffu, v, o);
    return v;
}

// packed f32x2 helpers (sm_100a)
__device__ __forceinline__ unsigned long long pack2(float lo, float hi) {
    unsigned long long r;
    asm("mov.b64 %0, {%1, %2};" : "=l"(r) : "f"(lo), "f"(hi));
    return r;
}
__device__ __forceinline__ void unpack2(unsigned long long v, float& lo, float& hi) {
    asm("mov.b64 {%0, %1}, %2;" : "=f"(lo), "=f"(hi) : "l"(v));
}
__device__ __forceinline__ unsigned long long fma2(unsigned long long a,
                                                   unsigned long long b,
                                                   unsigned long long c) {
    unsigned long long d;
    asm("fma.rn.f32x2 %0, %1, %2, %3;" : "=l"(d) : "l"(a), "l"(b), "l"(c));
    return d;
}
__device__ __forceinline__ unsigned long long add2(unsigned long long a,
                                                   unsigned long long b) {
    unsigned long long d;
    asm("add.rn.f32x2 %0, %1, %2;" : "=l"(d) : "l"(a), "l"(b));
    return d;
}

// ---------------------------------------------------------------------------
// P1: partial t = text @ Wg1 over a 32-channel tile. grid 129 x 256.
// blocks 0..127: b(8) x jhalf(2) x ctile(8); block 128: l min/max.
// ---------------------------------------------------------------------------
__global__ __launch_bounds__(256)
void p1_kernel(const float* __restrict__ text,
               const float* __restrict__ Wg1,
               const float* __restrict__ l)
{
    const int tid = threadIdx.x;
    const int blk = blockIdx.x;

    if (blk == 128) {
        __shared__ float rmx[8], rmn[8];
        float mx = -1e30f, mn = 1e30f;
        #pragma unroll
        for (int j = tid; j < HW; j += 256) {
            const float v = l[j];
            mx = fmaxf(mx, v);
            mn = fminf(mn, v);
        }
        #pragma unroll
        for (int o = 16; o; o >>= 1) {
            mx = fmaxf(mx, __shfl_xor_sync(0xffffffffu, mx, o));
            mn = fminf(mn, __shfl_xor_sync(0xffffffffu, mn, o));
        }
        if ((tid & 31) == 0) { rmx[tid >> 5] = mx; rmn[tid >> 5] = mn; }
        __syncthreads();
        if (tid == 0) {
            float a = rmx[0], b2 = rmn[0];
            #pragma unroll
            for (int k = 1; k < 8; k++) { a = fmaxf(a, rmx[k]); b2 = fminf(b2, rmn[k]); }
            g_lmax = a; g_lmin = b2;
        }
        return;
    }

    const int b  = blk >> 4;
    const int jh = (blk >> 3) & 1;
    const int ct = blk & 7;
    const int j  = jh * 256 + tid;

    __shared__ float text_s[32];
    if (tid < 32) text_s[tid] = text[b * C + ct * 32 + tid];
    __syncthreads();

    float acc = 0.0f;
    #pragma unroll
    for (int cc = 0; cc < 32; cc++) {
        acc = fmaf(text_s[cc], Wg1[(ct * 32 + cc) * C2 + j], acc);
    }
    g_tp[ct * (B * C2) + b * C2 + j] = acc;
}

// ---------------------------------------------------------------------------
// Fused prep: combine p1 partials + bias, LN + GELU, GvT = t@Wg2+bg2,
// vg = Wv@GvT, kg = Wk@GvT, wqk = kg@Wq, qb = bq.kg.
// One block per batch, 512 threads. ILP'd Wg2 loop; pipelined vg reductions.
// ---------------------------------------------------------------------------
__global__ __launch_bounds__(512)
void prep_kernel(const float* __restrict__ bg1,
                 const float* __restrict__ ln_g, const float* __restrict__ ln_b,
                 const float* __restrict__ Wg2,  const float* __restrict__ bg2,
                 const float* __restrict__ Wq,   const float* __restrict__ bq,
                 const float* __restrict__ Wk,   const float* __restrict__ Wv)
{
    const int b = blockIdx.x;
    const int tid = threadIdx.x;                 // 512 threads, 16 warps
    const int lane = tid & 31, wid = tid >> 5;

    __shared__ float t_s[C2];
    __shared__ float gv_s[C];
    __shared__ float part_f[2048];               // 8 k-chunks x 256 c
    __shared__ float kg_s[DK];
    __shared__ float red[16];
    __shared__ float bcast[2];

    // ---- combine p1 partials (fixed order: deterministic) ----
    float v = bg1[tid];
    #pragma unroll
    for (int ct = 0; ct < 8; ct++) v += g_tp[ct * (B * C2) + b * C2 + tid];

    // ---- LayerNorm + exact GELU ----
    float s1 = warp_sum(v);
    if (lane == 0) red[wid] = s1;
    __syncthreads();
    if (wid == 0) {
        float r = (lane < 16) ? red[lane] : 0.0f;
        r = warp_sum(r);
        if (lane == 0) bcast[0] = r * (1.0f / C2);
    }
    __syncthreads();
    const float mu = bcast[0];
    const float d = v - mu;
    float s2 = warp_sum(d * d);
    if (lane == 0) red[wid] = s2;
    __syncthreads();
    if (wid == 0) {
        float r = (lane < 16) ? red[lane] : 0.0f;
        r = warp_sum(r);
        if (lane == 0) bcast[1] = rsqrtf(r * (1.0f / C2) + 1e-5f);
    }
    __syncthreads();
    {
        float x = d * bcast[1] * ln_g[tid] + ln_b[tid];
        t_s[tid] = 0.5f * x * (1.0f + erff(x * 0.7071067811865476f));
    }
    __syncthreads();

    // ---- GvT[c] = sum_k t[k] * Wg2[k*C + c] + bg2[c] : 2-acc ILP ----
    {
        const int q = tid & 63;       // c-group: c = 4q .. 4q+3
        const int h = tid >> 6;       // k-chunk: k in [h*64, h*64+64)
        const float4* W4 = (const float4*)Wg2;   // [512][64] float4
        float4 a0 = make_float4(0.f, 0.f, 0.f, 0.f);
        float4 a1 = a0;
        const int k0 = h * 64;
        #pragma unroll 16
        for (int kk = 0; kk < 32; kk++) {
            const float t0 = t_s[k0 + kk];
            const float t1 = t_s[k0 + 32 + kk];
            const float4 w0 = W4[(k0 + kk) * 64 + q];
            const float4 w1 = W4[(k0 + 32 + kk) * 64 + q];
            a0.x = fmaf(t0, w0.x, a0.x); a0.y = fmaf(t0, w0.y, a0.y);
            a0.z = fmaf(t0, w0.z, a0.z); a0.w = fmaf(t0, w0.w, a0.w);
            a1.x = fmaf(t1, w1.x, a1.x); a1.y = fmaf(t1, w1.y, a1.y);
            a1.z = fmaf(t1, w1.z, a1.z); a1.w = fmaf(t1, w1.w, a1.w);
        }
        part_f[h * 256 + 4 * q + 0] = a0.x + a1.x;
        part_f[h * 256 + 4 * q + 1] = a0.y + a1.y;
        part_f[h * 256 + 4 * q + 2] = a0.z + a1.z;
        part_f[h * 256 + 4 * q + 3] = a0.w + a1.w;
    }
    __syncthreads();
    if (tid < C) {
        float g = bg2[tid];
        #pragma unroll
        for (int h = 0; h < 8; h++) g += part_f[h * 256 + tid];
        gv_s[tid] = g;
    }
    __syncthreads();

    // ---- vg[c] = Wv[c,:] . gv : warp per output, 16 outputs/warp,
    //      batched in groups of 8 so the 8 warp_sum shuffle trees pipeline ----
    {
        const float4* Wv4 = (const float4*)Wv;        // [256][64] float4
        const float4* gv4 = (const float4*)gv_s;
        const float4 gA = gv4[lane];
        const float4 gB = gv4[32 + lane];
        #pragma unroll
        for (int g = 0; g < 2; g++) {
            float part[8];
            #pragma unroll
            for (int oo = 0; oo < 8; oo++) {
                const int c = wid * 16 + g * 8 + oo;
                const float4 wA = Wv4[c * 64 + lane];
                const float4 wB = Wv4[c * 64 + 32 + lane];
                part[oo] = wA.x * gA.x + wA.y * gA.y + wA.z * gA.z + wA.w * gA.w
                         + wB.x * gB.x + wB.y * gB.y + wB.z * gB.z + wB.w * gB.w;
            }
            #pragma unroll
            for (int oo = 0; oo < 8; oo++) part[oo] = warp_sum(part[oo]);
            if (lane == 0) {
                #pragma unroll
                for (int oo = 0; oo < 8; oo++)
                    g_vg[b * C + wid * 16 + g * 8 + oo] = part[oo];
            }
        }
        // ---- kg[d] = Wk[d,:] . gv : 2 outputs/warp, batched ----
        const float4* Wk4 = (const float4*)Wk;        // [32][64] float4
        {
            float pk[2];
            #pragma unroll
            for (int oo = 0; oo < 2; oo++) {
                const int dd = wid * 2 + oo;
                const float4 wA = Wk4[dd * 64 + lane];
                const float4 wB = Wk4[dd * 64 + 32 + lane];
                pk[oo] = wA.x * gA.x + wA.y * gA.y + wA.z * gA.z + wA.w * gA.w
                       + wB.x * gB.x + wB.y * gB.y + wB.z * gB.z + wB.w * gB.w;
            }
            #pragma unroll
            for (int oo = 0; oo < 2; oo++) pk[oo] = warp_sum(pk[oo]);
            if (lane == 0) {
                kg_s[wid * 2 + 0] = pk[0];
                kg_s[wid * 2 + 1] = pk[1];
            }
        }
    }
    __syncthreads();

    // ---- wqk[c] = sum_d kg[d] * Wq[d*C + c];  qb = bq . kg ----
    if (tid < C) {
        float acc = 0.0f;
        #pragma unroll
        for (int dd = 0; dd < DK; dd++) acc = fmaf(kg_s[dd], Wq[dd * C + tid], acc);
        g_wqk[b * C + tid] = acc;
    }
    if (wid == 0) {
        float p = bq[lane] * kg_s[lane];
        p = warp_sum(p);
        if (lane == 0) g_qb[b] = p;
    }
}

// ---------------------------------------------------------------------------
// Attention: block = 256 thr = 8 warps; warp s = split s, lane = pixel.
// Thread owns channels [32s, 32s+32), img read ONCE (registers).
// occ-4 (one wave: 576 blocks <= 4*148) + f32x2-packed exp loop.
// grid (72, 8).
// ---------------------------------------------------------------------------
__global__ __launch_bounds__(256, 4)
void attn_kernel(const float* __restrict__ img,
                 const float* __restrict__ l,
                 const float* __restrict__ bv,
                 const float* __restrict__ gamma_p,
                 float* __restrict__ out)
{
    const int b = blockIdx.y;
    const int tid = threadIdx.x;
    const int p = tid & 31;      // pixel within block (lane)
    const int s = tid >> 5;      // split 0..7 (warp)
    const int i = blockIdx.x * 32 + p;
    const int c0 = s * 32;

    __shared__ float2 ls2[HW / 2];
    __shared__ float wq[C];
    __shared__ float vgs[C];
    __shared__ float bvs[C];
    __shared__ float partA[256];
    __shared__ float partS[256];
    __shared__ float partT[256];

    // front-batch img loads (32 contiguous channels per thread) into registers
    float im[32];
    const float* xb = img + (size_t)b * C * HW + (size_t)c0 * HW + i;
    #pragma unroll
    for (int cc = 0; cc < 32; cc++) im[cc] = xb[(size_t)cc * HW];

    const float gm   = *gamma_p;
    const float qb   = g_qb[b];
    const float lmax = g_lmax;
    const float lmin = g_lmin;

    // smem fills overlap the in-flight img loads
    {
        float* lsf = (float*)ls2;
        #pragma unroll
        for (int j = tid; j < HW; j += 256) lsf[j] = l[j];
    }
    wq[tid]  = g_wqk[b * C + tid];
    vgs[tid] = g_vg[b * C + tid];
    bvs[tid] = bv[tid];
    __syncthreads();

    // partial dot over this thread's 32 channels
    float a = 0.0f;
    #pragma unroll
    for (int cc = 0; cc < 32; cc++) a = fmaf(wq[c0 + cc], im[cc], a);
    partA[tid] = a;
    __syncthreads();
    float af = qb;
    #pragma unroll
    for (int k = 0; k < 8; k++) af += partA[k * 32 + p];

    // softmax-weighted sum of l (rank-1 logits), exp2 domain,
    // contiguous j chunk of 288 processed as 144 packed f32x2 pairs
    const float al = af * 1.4426950408889634f;
    const float m2 = (al > 0.0f) ? al * lmax : al * lmin;
    const unsigned long long al2  = pack2(al, al);
    const unsigned long long m2n2 = pack2(-m2, -m2);
    unsigned long long S2 = pack2(0.0f, 0.0f);
    unsigned long long T2 = S2;
    const int base2 = s * (HW / 16);   // float2 index of this split's chunk
    #pragma unroll 8
    for (int jj = 0; jj < HW / 16; jj++) {
        const float2 lj2f = ls2[base2 + jj];
        const unsigned long long lj2 = pack2(lj2f.x, lj2f.y);
        const unsigned long long u2 = fma2(al2, lj2, m2n2);
        float u0, u1;
        unpack2(u2, u0, u1);
        const unsigned long long e2 = pack2(ex2f(u0), ex2f(u1));
        S2 = add2(S2, e2);
        T2 = fma2(lj2, e2, T2);
    }
    float S0, S1, T0, T1;
    unpack2(S2, S0, S1);
    unpack2(T2, T0, T1);
    partS[tid] = S0 + S1;
    partT[tid] = T0 + T1;
    __syncthreads();
    float Ss = 0.0f, Ts = 0.0f;
    #pragma unroll
    for (int k = 0; k < 8; k++) {
        Ss += partS[k * 32 + p];
        Ts += partT[k * 32 + p];
    }
    const float sv = Ts / Ss;

    // out[b,c,i] = img + gamma * (vg[c]*sv + bv[c]) using register-cached img
    float* ob = out + (size_t)b * C * HW + (size_t)c0 * HW + i;
    #pragma unroll
    for (int cc = 0; cc < 32; cc++) {
        ob[(size_t)cc * HW] = fmaf(gm, fmaf(vgs[c0 + cc], sv, bvs[c0 + cc]), im[cc]);
    }
}

extern "C" void kernel_launch(void* const* d_in, const int* in_sizes, int n_in,
                              void* d_out, int out_size)
{
    const float* img   = (const float*)d_in[0];
    const float* text  = (const float*)d_in[1];
    const float* l     = (const float*)d_in[2];
    const float* Wg1   = (const float*)d_in[3];
    const float* bg1   = (const float*)d_in[4];
    const float* ln_g  = (const float*)d_in[5];
    const float* ln_b  = (const float*)d_in[6];
    const float* Wg2   = (const float*)d_in[7];
    const float* bg2   = (const float*)d_in[8];
    const float* Wq    = (const float*)d_in[9];
    const float* bq    = (const float*)d_in[10];
    const float* Wk    = (const float*)d_in[11];
    // d_in[12] = bk : cancels in softmax, unused
    const float* Wv    = (const float*)d_in[13];
    const float* bv    = (const float*)d_in[14];
    const float* gamma = (const float*)d_in[15];
    float* out = (float*)d_out;

    p1_kernel<<<129, 256>>>(text, Wg1, l);
    prep_kernel<<<B, 512>>>(bg1, ln_g, ln_b, Wg2, bg2, Wq, bq, Wk, Wv);
    dim3 grid(HW / 32, B);
    attn_kernel<<<grid, 256>>>(img, l, bv, gamma, out);
}

// round 14
// speedup vs baseline: 1.5547x; 1.2201x over previous
#include <cuda_runtime.h>
#include <cuda_bf16.h>

#define B 8
#define C 256
#define HW 2304
#define DK 32
#define C2 512

#define M_TAB 4096
#define ALPHA 8.0f
#define PI_F 3.14159265358979323846f

// Scratch (device globals — no allocation allowed)
__device__ float g_tp[8 * B * C2]; // p1 partials: [ct][b][j]
__device__ float g_vg[B * C];      // vg = Wv @ GvT
__device__ float g_wqk[B * C];     // wqk = kg @ Wq
__device__ float g_qb[B];          // qb = bq . kg
__device__ float g_tab[M_TAB];     // s(a) table on a = ALPHA*tan(u) grid

__device__ __forceinline__ float ex2f(float x) {
    float y;
    asm("ex2.approx.ftz.f32 %0, %1;" : "=f"(y) : "f"(x));
    return y;
}

__device__ __forceinline__ float warp_sum(float v) {
    #pragma unroll
    for (int o = 16; o; o >>= 1) v += __shfl_xor_sync(0xffffffffu, v, o);
    return v;
}

// ---------------------------------------------------------------------------
// Stage 1: grid 640 x 256.
// blocks 0..127  : p1 partial t = text @ Wg1 over a 32-channel tile.
// blocks 128..639: s(a) table build — 8 entries per block, one per warp.
//                  Table depends only on l; fully parallel with p1.
// ---------------------------------------------------------------------------
__global__ __launch_bounds__(256)
void stage1_kernel(const float* __restrict__ text,
                   const float* __restrict__ Wg1,
                   const float* __restrict__ l)
{
    const int tid = threadIdx.x;
    const int blk = blockIdx.x;
    const int lane = tid & 31, wid = tid >> 5;

    if (blk >= 128) {
        // ---- table block ----
        const int tblk = blk - 128;              // 0..511
        __shared__ float ls[HW];
        __shared__ float rmx[8], rmn[8];

        float mx = -1e30f, mn = 1e30f;
        #pragma unroll
        for (int j = tid; j < HW; j += 256) {
            const float v = l[j];
            ls[j] = v;
            mx = fmaxf(mx, v);
            mn = fminf(mn, v);
        }
        #pragma unroll
        for (int o = 16; o; o >>= 1) {
            mx = fmaxf(mx, __shfl_xor_sync(0xffffffffu, mx, o));
            mn = fminf(mn, __shfl_xor_sync(0xffffffffu, mn, o));
        }
        if (lane == 0) { rmx[wid] = mx; rmn[wid] = mn; }
        __syncthreads();
        float lmax = rmx[0], lmin = rmn[0];
        #pragma unroll
        for (int k = 1; k < 8; k++) {
            lmax = fmaxf(lmax, rmx[k]);
            lmin = fminf(lmin, rmn[k]);
        }

        // warp wid computes table entry e
        const int e = tblk * 8 + wid;
        const float u = (e + 0.5f) * (PI_F / M_TAB) - 0.5f * PI_F;
        const float a = ALPHA * tanf(u);
        const float al = a * 1.4426950408889634f;        // log2 domain
        const float m2 = (al > 0.0f) ? al * lmax : al * lmin;
        float S = 0.0f, T = 0.0f;
        #pragma unroll 8
        for (int j = lane; j < HW; j += 32) {
            const float lj = ls[j];
            const float ev = ex2f(fmaf(al, lj, -m2));
            S += ev;
            T = fmaf(lj, ev, T);
        }
        S = warp_sum(S);
        T = warp_sum(T);
        if (lane == 0) g_tab[e] = T / S;
        return;
    }

    // ---- p1 block ----
    const int b  = blk >> 4;
    const int jh = (blk >> 3) & 1;
    const int ct = blk & 7;
    const int j  = jh * 256 + tid;

    __shared__ float text_s[32];
    if (tid < 32) text_s[tid] = text[b * C + ct * 32 + tid];
    __syncthreads();

    float acc = 0.0f;
    #pragma unroll
    for (int cc = 0; cc < 32; cc++) {
        acc = fmaf(text_s[cc], Wg1[(ct * 32 + cc) * C2 + j], acc);
    }
    g_tp[ct * (B * C2) + b * C2 + j] = acc;
}

// ---------------------------------------------------------------------------
// Fused prep: combine p1 partials + bias, LN + GELU, GvT = t@Wg2+bg2,
// vg = Wv@GvT, kg = Wk@GvT, wqk = kg@Wq, qb = bq.kg.
// One block per batch, 512 threads. (R12 structure, measured best.)
// ---------------------------------------------------------------------------
__global__ __launch_bounds__(512)
void prep_kernel(const float* __restrict__ bg1,
                 const float* __restrict__ ln_g, const float* __restrict__ ln_b,
                 const float* __restrict__ Wg2,  const float* __restrict__ bg2,
                 const float* __restrict__ Wq,   const float* __restrict__ bq,
                 const float* __restrict__ Wk,   const float* __restrict__ Wv)
{
    const int b = blockIdx.x;
    const int tid = threadIdx.x;                 // 512 threads, 16 warps
    const int lane = tid & 31, wid = tid >> 5;

    __shared__ float t_s[C2];
    __shared__ float gv_s[C];
    __shared__ float part_f[2048];               // 8 k-chunks x 256 c
    __shared__ float kg_s[DK];
    __shared__ float red[16];
    __shared__ float bcast[2];

    // ---- combine p1 partials (fixed order: deterministic) ----
    float v = bg1[tid];
    #pragma unroll
    for (int ct = 0; ct < 8; ct++) v += g_tp[ct * (B * C2) + b * C2 + tid];

    // ---- LayerNorm + exact GELU ----
    float s1 = warp_sum(v);
    if (lane == 0) red[wid] = s1;
    __syncthreads();
    if (wid == 0) {
        float r = (lane < 16) ? red[lane] : 0.0f;
        r = warp_sum(r);
        if (lane == 0) bcast[0] = r * (1.0f / C2);
    }
    __syncthreads();
    const float mu = bcast[0];
    const float d = v - mu;
    float s2 = warp_sum(d * d);
    if (lane == 0) red[wid] = s2;
    __syncthreads();
    if (wid == 0) {
        float r = (lane < 16) ? red[lane] : 0.0f;
        r = warp_sum(r);
        if (lane == 0) bcast[1] = rsqrtf(r * (1.0f / C2) + 1e-5f);
    }
    __syncthreads();
    {
        float x = d * bcast[1] * ln_g[tid] + ln_b[tid];
        t_s[tid] = 0.5f * x * (1.0f + erff(x * 0.7071067811865476f));
    }
    __syncthreads();

    // ---- GvT[c] = sum_k t[k] * Wg2[k*C + c] + bg2[c] : 2-acc ILP ----
    {
        const int q = tid & 63;       // c-group: c = 4q .. 4q+3
        const int h = tid >> 6;       // k-chunk: k in [h*64, h*64+64)
        const float4* W4 = (const float4*)Wg2;   // [512][64] float4
        float4 a0 = make_float4(0.f, 0.f, 0.f, 0.f);
        float4 a1 = a0;
        const int k0 = h * 64;
        #pragma unroll 16
        for (int kk = 0; kk < 32; kk++) {
            const float t0 = t_s[k0 + kk];
            const float t1 = t_s[k0 + 32 + kk];
            const float4 w0 = W4[(k0 + kk) * 64 + q];
            const float4 w1 = W4[(k0 + 32 + kk) * 64 + q];
            a0.x = fmaf(t0, w0.x, a0.x); a0.y = fmaf(t0, w0.y, a0.y);
            a0.z = fmaf(t0, w0.z, a0.z); a0.w = fmaf(t0, w0.w, a0.w);
            a1.x = fmaf(t1, w1.x, a1.x); a1.y = fmaf(t1, w1.y, a1.y);
            a1.z = fmaf(t1, w1.z, a1.z); a1.w = fmaf(t1, w1.w, a1.w);
        }
        part_f[h * 256 + 4 * q + 0] = a0.x + a1.x;
        part_f[h * 256 + 4 * q + 1] = a0.y + a1.y;
        part_f[h * 256 + 4 * q + 2] = a0.z + a1.z;
        part_f[h * 256 + 4 * q + 3] = a0.w + a1.w;
    }
    __syncthreads();
    if (tid < C) {
        float g = bg2[tid];
        #pragma unroll
        for (int h = 0; h < 8; h++) g += part_f[h * 256 + tid];
        gv_s[tid] = g;
    }
    __syncthreads();

    // ---- vg[c] = Wv[c,:] . gv : 16 outputs/warp, pipelined reductions ----
    {
        const float4* Wv4 = (const float4*)Wv;        // [256][64] float4
        const float4* gv4 = (const float4*)gv_s;
        const float4 gA = gv4[lane];
        const float4 gB = gv4[32 + lane];
        #pragma unroll
        for (int g = 0; g < 2; g++) {
            float part[8];
            #pragma unroll
            for (int oo = 0; oo < 8; oo++) {
                const int c = wid * 16 + g * 8 + oo;
                const float4 wA = Wv4[c * 64 + lane];
                const float4 wB = Wv4[c * 64 + 32 + lane];
                part[oo] = wA.x * gA.x + wA.y * gA.y + wA.z * gA.z + wA.w * gA.w
                         + wB.x * gB.x + wB.y * gB.y + wB.z * gB.z + wB.w * gB.w;
            }
            #pragma unroll
            for (int oo = 0; oo < 8; oo++) part[oo] = warp_sum(part[oo]);
            if (lane == 0) {
                #pragma unroll
                for (int oo = 0; oo < 8; oo++)
                    g_vg[b * C + wid * 16 + g * 8 + oo] = part[oo];
            }
        }
        // ---- kg[d] = Wk[d,:] . gv : 2 outputs/warp ----
        const float4* Wk4 = (const float4*)Wk;        // [32][64] float4
        {
            float pk[2];
            #pragma unroll
            for (int oo = 0; oo < 2; oo++) {
                const int dd = wid * 2 + oo;
                const float4 wA = Wk4[dd * 64 + lane];
                const float4 wB = Wk4[dd * 64 + 32 + lane];
                pk[oo] = wA.x * gA.x + wA.y * gA.y + wA.z * gA.z + wA.w * gA.w
                       + wB.x * gB.x + wB.y * gB.y + wB.z * gB.z + wB.w * gB.w;
            }
            #pragma unroll
            for (int oo = 0; oo < 2; oo++) pk[oo] = warp_sum(pk[oo]);
            if (lane == 0) {
                kg_s[wid * 2 + 0] = pk[0];
                kg_s[wid * 2 + 1] = pk[1];
            }
        }
    }
    __syncthreads();

    // ---- wqk[c] = sum_d kg[d] * Wq[d*C + c];  qb = bq . kg ----
    if (tid < C) {
        float acc = 0.0f;
        #pragma unroll
        for (int dd = 0; dd < DK; dd++) acc = fmaf(kg_s[dd], Wq[dd * C + tid], acc);
        g_wqk[b * C + tid] = acc;
    }
    if (wid == 0) {
        float p = bq[lane] * kg_s[lane];
        p = warp_sum(p);
        if (lane == 0) g_qb[b] = p;
    }
}

// ---------------------------------------------------------------------------
// Attention: pure memory stream now. block = 256 thr; warp s owns channels
// [32s, 32s+32) for the block's 32 pixels (lane = pixel). img read ONCE into
// registers; s(a) via 4-tap Catmull-Rom from the smem-cached table.
// grid (72, 8), occ 4.
// ---------------------------------------------------------------------------
__global__ __launch_bounds__(256, 4)
void attn_kernel(const float* __restrict__ img,
                 const float* __restrict__ bv,
                 const float* __restrict__ gamma_p,
                 float* __restrict__ out)
{
    const int b = blockIdx.y;
    const int tid = threadIdx.x;
    const int p = tid & 31;      // pixel within block (lane)
    const int s = tid >> 5;      // channel-split 0..7 (warp)
    const int i = blockIdx.x * 32 + p;
    const int c0 = s * 32;

    __shared__ float tab_s[M_TAB];
    __shared__ float wq[C];
    __shared__ float vgs[C];
    __shared__ float bvs[C];
    __shared__ float partA[256];

    // front-batch img loads (32 contiguous channels per thread) into registers
    float im[32];
    const float* xb = img + (size_t)b * C * HW + (size_t)c0 * HW + i;
    #pragma unroll
    for (int cc = 0; cc < 32; cc++) im[cc] = xb[(size_t)cc * HW];

    const float gm = *gamma_p;
    const float qb = g_qb[b];

    // smem fills overlap the in-flight img loads
    #pragma unroll
    for (int k = tid; k < M_TAB; k += 256) tab_s[k] = g_tab[k];
    wq[tid]  = g_wqk[b * C + tid];
    vgs[tid] = g_vg[b * C + tid];
    bvs[tid] = bv[tid];
    __syncthreads();

    // partial dot over this thread's 32 channels
    float a = 0.0f;
    #pragma unroll
    for (int cc = 0; cc < 32; cc++) a = fmaf(wq[c0 + cc], im[cc], a);
    partA[tid] = a;
    __syncthreads();
    float af = qb;
    #pragma unroll
    for (int k = 0; k < 8; k++) af += partA[k * 32 + p];

    // s(af) via table: u = atan(af/ALPHA); cubic Catmull-Rom in u-grid
    const float u = atanf(af * (1.0f / ALPHA));
    const float idx = u * (M_TAB / PI_F) + (M_TAB * 0.5f - 0.5f);
    const float fi = floorf(idx);
    const float t = idx - fi;
    const int i1 = (int)fi;
    const int j0 = max(i1 - 1, 0);
    const int j1 = min(max(i1, 0), M_TAB - 1);
    const int j2 = min(i1 + 1, M_TAB - 1);
    const int j3 = min(i1 + 2, M_TAB - 1);
    const float p0 = tab_s[j0], p1v = tab_s[j1], p2 = tab_s[j2], p3 = tab_s[j3];
    const float sv = p1v + 0.5f * t * (p2 - p0
                   + t * (2.0f * p0 - 5.0f * p1v + 4.0f * p2 - p3
                   + t * (3.0f * (p1v - p2) + p3 - p0)));

    // out[b,c,i] = img + gamma * (vg[c]*sv + bv[c]) using register-cached img
    float* ob = out + (size_t)b * C * HW + (size_t)c0 * HW + i;
    #pragma unroll
    for (int cc = 0; cc < 32; cc++) {
        ob[(size_t)cc * HW] = fmaf(gm, fmaf(vgs[c0 + cc], sv, bvs[c0 + cc]), im[cc]);
    }
}

extern "C" void kernel_launch(void* const* d_in, const int* in_sizes, int n_in,
                              void* d_out, int out_size)
{
    const float* img   = (const float*)d_in[0];
    const float* text  = (const float*)d_in[1];
    const float* l     = (const float*)d_in[2];
    const float* Wg1   = (const float*)d_in[3];
    const float* bg1   = (const float*)d_in[4];
    const float* ln_g  = (const float*)d_in[5];
    const float* ln_b  = (const float*)d_in[6];
    const float* Wg2   = (const float*)d_in[7];
    const float* bg2   = (const float*)d_in[8];
    const float* Wq    = (const float*)d_in[9];
    const float* bq    = (const float*)d_in[10];
    const float* Wk    = (const float*)d_in[11];
    // d_in[12] = bk : cancels in softmax, unused
    const float* Wv    = (const float*)d_in[13];
    const float* bv    = (const float*)d_in[14];
    const float* gamma = (const float*)d_in[15];
    float* out = (float*)d_out;

    stage1_kernel<<<640, 256>>>(text, Wg1, l);
    prep_kernel<<<B, 512>>>(bg1, ln_g, ln_b, Wg2, bg2, Wq, bq, Wk, Wv);
    dim3 grid(HW / 32, B);
    attn_kernel<<<grid, 256>>>(img, bv, gamma, out);
}

// round 15
// speedup vs baseline: 1.6558x; 1.0650x over previous
#include <cuda_runtime.h>
#include <cuda_bf16.h>

#define B 8
#define C 256
#define HW 2304
#define DK 32
#define C2 512

#define M_TAB 2048
#define ALPHA 8.0f
#define PI_F 3.14159265358979323846f

#define NTABBLK 128   // table blocks; each computes 16 entries (2 per warp)

// Scratch (device globals — no allocation allowed)
__device__ float g_tp[8 * B * C2]; // p1 partials: [ct][b][j]
__device__ float g_vg[B * C];      // vg = Wv @ GvT
__device__ float g_wqk[B * C];     // wqk = kg @ Wq
__device__ float g_qb[B];          // qb = bq . kg
__device__ float g_tab[M_TAB];     // s(a) table on a = ALPHA*tan(u) grid

__device__ __forceinline__ float ex2f(float x) {
    float y;
    asm("ex2.approx.ftz.f32 %0, %1;" : "=f"(y) : "f"(x));
    return y;
}

__device__ __forceinline__ float warp_sum(float v) {
    #pragma unroll
    for (int o = 16; o; o >>= 1) v += __shfl_xor_sync(0xffffffffu, v, o);
    return v;
}

// ---------------------------------------------------------------------------
// Stage 1: grid 256 x 256.
// blocks 0..127  : p1 partial t = text @ Wg1 over a 32-channel tile.
// blocks 128..255: s(a) table build — 16 entries per block, 2 per warp
//                  (interleaved EX2 chains pipeline the MUFU).
// ---------------------------------------------------------------------------
__global__ __launch_bounds__(256)
void stage1_kernel(const float* __restrict__ text,
                   const float* __restrict__ Wg1,
                   const float* __restrict__ l)
{
    const int tid = threadIdx.x;
    const int blk = blockIdx.x;
    const int lane = tid & 31, wid = tid >> 5;

    if (blk >= 128) {
        // ---- table block ----
        const int tblk = blk - 128;              // 0..127
        __shared__ float ls[HW];
        __shared__ float rmx[8], rmn[8];

        float mx = -1e30f, mn = 1e30f;
        #pragma unroll
        for (int j = tid; j < HW; j += 256) {
            const float v = l[j];
            ls[j] = v;
            mx = fmaxf(mx, v);
            mn = fminf(mn, v);
        }
        #pragma unroll
        for (int o = 16; o; o >>= 1) {
            mx = fmaxf(mx, __shfl_xor_sync(0xffffffffu, mx, o));
            mn = fminf(mn, __shfl_xor_sync(0xffffffffu, mn, o));
        }
        if (lane == 0) { rmx[wid] = mx; rmn[wid] = mn; }
        __syncthreads();
        float lmax = rmx[0], lmin = rmn[0];
        #pragma unroll
        for (int k = 1; k < 8; k++) {
            lmax = fmaxf(lmax, rmx[k]);
            lmin = fminf(lmin, rmn[k]);
        }

        // warp wid computes entries e0 = tblk*16 + 2*wid, e1 = e0 + 1
        const int e0 = tblk * 16 + 2 * wid;
        const float u0 = (e0 + 0.5f) * (PI_F / M_TAB) - 0.5f * PI_F;
        const float u1 = (e0 + 1.5f) * (PI_F / M_TAB) - 0.5f * PI_F;
        const float al0 = ALPHA * tanf(u0) * 1.4426950408889634f;
        const float al1 = ALPHA * tanf(u1) * 1.4426950408889634f;
        const float m20 = (al0 > 0.0f) ? al0 * lmax : al0 * lmin;
        const float m21 = (al1 > 0.0f) ? al1 * lmax : al1 * lmin;
        float S0 = 0.0f, T0 = 0.0f, S1 = 0.0f, T1 = 0.0f;
        #pragma unroll 8
        for (int j = lane; j < HW; j += 32) {
            const float lj = ls[j];
            const float ev0 = ex2f(fmaf(al0, lj, -m20));
            const float ev1 = ex2f(fmaf(al1, lj, -m21));
            S0 += ev0;
            T0 = fmaf(lj, ev0, T0);
            S1 += ev1;
            T1 = fmaf(lj, ev1, T1);
        }
        S0 = warp_sum(S0);
        T0 = warp_sum(T0);
        S1 = warp_sum(S1);
        T1 = warp_sum(T1);
        if (lane == 0) {
            g_tab[e0]     = T0 / S0;
            g_tab[e0 + 1] = T1 / S1;
        }
        return;
    }

    // ---- p1 block ----
    const int b  = blk >> 4;
    const int jh = (blk >> 3) & 1;
    const int ct = blk & 7;
    const int j  = jh * 256 + tid;

    __shared__ float text_s[32];
    if (tid < 32) text_s[tid] = text[b * C + ct * 32 + tid];
    __syncthreads();

    float acc = 0.0f;
    #pragma unroll
    for (int cc = 0; cc < 32; cc++) {
        acc = fmaf(text_s[cc], Wg1[(ct * 32 + cc) * C2 + j], acc);
    }
    g_tp[ct * (B * C2) + b * C2 + j] = acc;
}

// ---------------------------------------------------------------------------
// Fused prep: combine p1 partials + bias, LN + GELU, GvT = t@Wg2+bg2,
// vg = Wv@GvT, kg = Wk@GvT, wqk = kg@Wq, qb = bq.kg.
// One block per batch, 512 threads. (R12 structure, measured best.)
// ---------------------------------------------------------------------------
__global__ __launch_bounds__(512)
void prep_kernel(const float* __restrict__ bg1,
                 const float* __restrict__ ln_g, const float* __restrict__ ln_b,
                 const float* __restrict__ Wg2,  const float* __restrict__ bg2,
                 const float* __restrict__ Wq,   const float* __restrict__ bq,
                 const float* __restrict__ Wk,   const float* __restrict__ Wv)
{
    const int b = blockIdx.x;
    const int tid = threadIdx.x;                 // 512 threads, 16 warps
    const int lane = tid & 31, wid = tid >> 5;

    __shared__ float t_s[C2];
    __shared__ float gv_s[C];
    __shared__ float part_f[2048];               // 8 k-chunks x 256 c
    __shared__ float kg_s[DK];
    __shared__ float red[16];
    __shared__ float bcast[2];

    // ---- combine p1 partials (fixed order: deterministic) ----
    float v = bg1[tid];
    #pragma unroll
    for (int ct = 0; ct < 8; ct++) v += g_tp[ct * (B * C2) + b * C2 + tid];

    // ---- LayerNorm + exact GELU ----
    float s1 = warp_sum(v);
    if (lane == 0) red[wid] = s1;
    __syncthreads();
    if (wid == 0) {
        float r = (lane < 16) ? red[lane] : 0.0f;
        r = warp_sum(r);
        if (lane == 0) bcast[0] = r * (1.0f / C2);
    }
    __syncthreads();
    const float mu = bcast[0];
    const float d = v - mu;
    float s2 = warp_sum(d * d);
    if (lane == 0) red[wid] = s2;
    __syncthreads();
    if (wid == 0) {
        float r = (lane < 16) ? red[lane] : 0.0f;
        r = warp_sum(r);
        if (lane == 0) bcast[1] = rsqrtf(r * (1.0f / C2) + 1e-5f);
    }
    __syncthreads();
    {
        float x = d * bcast[1] * ln_g[tid] + ln_b[tid];
        t_s[tid] = 0.5f * x * (1.0f + erff(x * 0.7071067811865476f));
    }
    __syncthreads();

    // ---- GvT[c] = sum_k t[k] * Wg2[k*C + c] + bg2[c] : 2-acc ILP ----
    {
        const int q = tid & 63;       // c-group: c = 4q .. 4q+3
        const int h = tid >> 6;       // k-chunk: k in [h*64, h*64+64)
        const float4* W4 = (const float4*)Wg2;   // [512][64] float4
        float4 a0 = make_float4(0.f, 0.f, 0.f, 0.f);
        float4 a1 = a0;
        const int k0 = h * 64;
        #pragma unroll 16
        for (int kk = 0; kk < 32; kk++) {
            const float t0 = t_s[k0 + kk];
            const float t1 = t_s[k0 + 32 + kk];
            const float4 w0 = W4[(k0 + kk) * 64 + q];
            const float4 w1 = W4[(k0 + 32 + kk) * 64 + q];
            a0.x = fmaf(t0, w0.x, a0.x); a0.y = fmaf(t0, w0.y, a0.y);
            a0.z = fmaf(t0, w0.z, a0.z); a0.w = fmaf(t0, w0.w, a0.w);
            a1.x = fmaf(t1, w1.x, a1.x); a1.y = fmaf(t1, w1.y, a1.y);
            a1.z = fmaf(t1, w1.z, a1.z); a1.w = fmaf(t1, w1.w, a1.w);
        }
        part_f[h * 256 + 4 * q + 0] = a0.x + a1.x;
        part_f[h * 256 + 4 * q + 1] = a0.y + a1.y;
        part_f[h * 256 + 4 * q + 2] = a0.z + a1.z;
        part_f[h * 256 + 4 * q + 3] = a0.w + a1.w;
    }
    __syncthreads();
    if (tid < C) {
        float g = bg2[tid];
        #pragma unroll
        for (int h = 0; h < 8; h++) g += part_f[h * 256 + tid];
        gv_s[tid] = g;
    }
    __syncthreads();

    // ---- vg[c] = Wv[c,:] . gv : 16 outputs/warp, pipelined reductions ----
    {
        const float4* Wv4 = (const float4*)Wv;        // [256][64] float4
        const float4* gv4 = (const float4*)gv_s;
        const float4 gA = gv4[lane];
        const float4 gB = gv4[32 + lane];
        #pragma unroll
        for (int g = 0; g < 2; g++) {
            float part[8];
            #pragma unroll
            for (int oo = 0; oo < 8; oo++) {
                const int c = wid * 16 + g * 8 + oo;
                const float4 wA = Wv4[c * 64 + lane];
                const float4 wB = Wv4[c * 64 + 32 + lane];
                part[oo] = wA.x * gA.x + wA.y * gA.y + wA.z * gA.z + wA.w * gA.w
                         + wB.x * gB.x + wB.y * gB.y + wB.z * gB.z + wB.w * gB.w;
            }
            #pragma unroll
            for (int oo = 0; oo < 8; oo++) part[oo] = warp_sum(part[oo]);
            if (lane == 0) {
                #pragma unroll
                for (int oo = 0; oo < 8; oo++)
                    g_vg[b * C + wid * 16 + g * 8 + oo] = part[oo];
            }
        }
        // ---- kg[d] = Wk[d,:] . gv : 2 outputs/warp ----
        const float4* Wk4 = (const float4*)Wk;        // [32][64] float4
        {
            float pk[2];
            #pragma unroll
            for (int oo = 0; oo < 2; oo++) {
                const int dd = wid * 2 + oo;
                const float4 wA = Wk4[dd * 64 + lane];
                const float4 wB = Wk4[dd * 64 + 32 + lane];
                pk[oo] = wA.x * gA.x + wA.y * gA.y + wA.z * gA.z + wA.w * gA.w
                       + wB.x * gB.x + wB.y * gB.y + wB.z * gB.z + wB.w * gB.w;
            }
            #pragma unroll
            for (int oo = 0; oo < 2; oo++) pk[oo] = warp_sum(pk[oo]);
            if (lane == 0) {
                kg_s[wid * 2 + 0] = pk[0];
                kg_s[wid * 2 + 1] = pk[1];
            }
        }
    }
    __syncthreads();

    // ---- wqk[c] = sum_d kg[d] * Wq[d*C + c];  qb = bq . kg ----
    if (tid < C) {
        float acc = 0.0f;
        #pragma unroll
        for (int dd = 0; dd < DK; dd++) acc = fmaf(kg_s[dd], Wq[dd * C + tid], acc);
        g_wqk[b * C + tid] = acc;
    }
    if (wid == 0) {
        float p = bq[lane] * kg_s[lane];
        p = warp_sum(p);
        if (lane == 0) g_qb[b] = p;
    }
}

// ---------------------------------------------------------------------------
// Attention: pure memory stream. block = 256 thr; warp s owns channels
// [32s, 32s+32) for the block's 32 pixels (lane = pixel). img read ONCE into
// registers; s(a) via 4-tap Catmull-Rom from the smem-cached table.
// grid (72, 8), occ 4.
// ---------------------------------------------------------------------------
__global__ __launch_bounds__(256, 4)
void attn_kernel(const float* __restrict__ img,
                 const float* __restrict__ bv,
                 const float* __restrict__ gamma_p,
                 float* __restrict__ out)
{
    const int b = blockIdx.y;
    const int tid = threadIdx.x;
    const int p = tid & 31;      // pixel within block (lane)
    const int s = tid >> 5;      // channel-split 0..7 (warp)
    const int i = blockIdx.x * 32 + p;
    const int c0 = s * 32;

    __shared__ float tab_s[M_TAB];
    __shared__ float wq[C];
    __shared__ float vgs[C];
    __shared__ float bvs[C];
    __shared__ float partA[256];

    // front-batch img loads (32 contiguous channels per thread) into registers
    float im[32];
    const float* xb = img + (size_t)b * C * HW + (size_t)c0 * HW + i;
    #pragma unroll
    for (int cc = 0; cc < 32; cc++) im[cc] = xb[(size_t)cc * HW];

    const float gm = *gamma_p;
    const float qb = g_qb[b];

    // smem fills overlap the in-flight img loads
    #pragma unroll
    for (int k = tid; k < M_TAB; k += 256) tab_s[k] = g_tab[k];
    wq[tid]  = g_wqk[b * C + tid];
    vgs[tid] = g_vg[b * C + tid];
    bvs[tid] = bv[tid];
    __syncthreads();

    // partial dot over this thread's 32 channels
    float a = 0.0f;
    #pragma unroll
    for (int cc = 0; cc < 32; cc++) a = fmaf(wq[c0 + cc], im[cc], a);
    partA[tid] = a;
    __syncthreads();
    float af = qb;
    #pragma unroll
    for (int k = 0; k < 8; k++) af += partA[k * 32 + p];

    // s(af) via table: u = atan(af/ALPHA); cubic Catmull-Rom in u-grid
    const float u = atanf(af * (1.0f / ALPHA));
    const float idx = u * (M_TAB / PI_F) + (M_TAB * 0.5f - 0.5f);
    const float fi = floorf(idx);
    const float t = idx - fi;
    const int i1 = (int)fi;
    const int j0 = max(i1 - 1, 0);
    const int j1 = min(max(i1, 0), M_TAB - 1);
    const int j2 = min(i1 + 1, M_TAB - 1);
    const int j3 = min(i1 + 2, M_TAB - 1);
    const float p0 = tab_s[j0], p1v = tab_s[j1], p2 = tab_s[j2], p3 = tab_s[j3];
    const float sv = p1v + 0.5f * t * (p2 - p0
                   + t * (2.0f * p0 - 5.0f * p1v + 4.0f * p2 - p3
                   + t * (3.0f * (p1v - p2) + p3 - p0)));

    // out[b,c,i] = img + gamma * (vg[c]*sv + bv[c]) using register-cached img
    float* ob = out + (size_t)b * C * HW + (size_t)c0 * HW + i;
    #pragma unroll
    for (int cc = 0; cc < 32; cc++) {
        ob[(size_t)cc * HW] = fmaf(gm, fmaf(vgs[c0 + cc], sv, bvs[c0 + cc]), im[cc]);
    }
}

extern "C" void kernel_launch(void* const* d_in, const int* in_sizes, int n_in,
                              void* d_out, int out_size)
{
    const float* img   = (const float*)d_in[0];
    const float* text  = (const float*)d_in[1];
    const float* l     = (const float*)d_in[2];
    const float* Wg1   = (const float*)d_in[3];
    const float* bg1   = (const float*)d_in[4];
    const float* ln_g  = (const float*)d_in[5];
    const float* ln_b  = (const float*)d_in[6];
    const float* Wg2   = (const float*)d_in[7];
    const float* bg2   = (const float*)d_in[8];
    const float* Wq    = (const float*)d_in[9];
    const float* bq    = (const float*)d_in[10];
    const float* Wk    = (const float*)d_in[11];
    // d_in[12] = bk : cancels in softmax, unused
    const float* Wv    = (const float*)d_in[13];
    const float* bv    = (const float*)d_in[14];
    const float* gamma = (const float*)d_in[15];
    float* out = (float*)d_out;

    stage1_kernel<<<128 + NTABBLK, 256>>>(text, Wg1, l);
    prep_kernel<<<B, 512>>>(bg1, ln_g, ln_b, Wg2, bg2, Wq, bq, Wk, Wv);
    dim3 grid(HW / 32, B);
    attn_kernel<<<grid, 256>>>(img, bv, gamma, out);
}

// round 16
// speedup vs baseline: 1.8771x; 1.1336x over previous
#include <cuda_runtime.h>
#include <cuda_bf16.h>

#define B 8
#define C 256
#define HW 2304
#define DK 32
#define C2 512

#define M_TAB 2048
#define ALPHA 8.0f
#define PI_F 3.14159265358979323846f

#define NTABBLK 128   // table blocks (in prep grid); 16 entries each (2/warp)

// Scratch (device globals — no allocation allowed)
__device__ float g_tp[8 * B * C2]; // p1 partials: [ct][b][j]
__device__ float g_vg[B * C];      // vg = Wv @ GvT
__device__ float g_wqk[B * C];     // wqk = kg @ Wq
__device__ float g_qb[B];          // qb = bq . kg
__device__ float g_tab[M_TAB];     // s(a) table on a = ALPHA*tan(u) grid

__device__ __forceinline__ float ex2f(float x) {
    float y;
    asm("ex2.approx.ftz.f32 %0, %1;" : "=f"(y) : "f"(x));
    return y;
}

__device__ __forceinline__ float warp_sum(float v) {
    #pragma unroll
    for (int o = 16; o; o >>= 1) v += __shfl_xor_sync(0xffffffffu, v, o);
    return v;
}

// ---------------------------------------------------------------------------
// P1: partial t = text @ Wg1 over a 32-channel tile. grid 128 x 256.
// blocks: b(8) x jhalf(2) x ctile(8).
// ---------------------------------------------------------------------------
__global__ __launch_bounds__(256)
void p1_kernel(const float* __restrict__ text,
               const float* __restrict__ Wg1)
{
    const int tid = threadIdx.x;
    const int blk = blockIdx.x;

    const int b  = blk >> 4;
    const int jh = (blk >> 3) & 1;
    const int ct = blk & 7;
    const int j  = jh * 256 + tid;

    __shared__ float text_s[32];
    if (tid < 32) text_s[tid] = text[b * C + ct * 32 + tid];
    __syncthreads();

    float acc = 0.0f;
    #pragma unroll
    for (int cc = 0; cc < 32; cc++) {
        acc = fmaf(text_s[cc], Wg1[(ct * 32 + cc) * C2 + j], acc);
    }
    g_tp[ct * (B * C2) + b * C2 + j] = acc;
}

// ---------------------------------------------------------------------------
// Prep + table kernel: grid (B + NTABBLK) x mixed thread counts.
// blocks 0..7   : per-batch text-branch combine (512 threads of work)
// blocks 8..135 : s(a) table build (runs on otherwise-idle SMs, parallel
//                 with the 8 prep blocks; table feeds only attn)
// ---------------------------------------------------------------------------
__global__ __launch_bounds__(512)
void prep_kernel(const float* __restrict__ l,
                 const float* __restrict__ bg1,
                 const float* __restrict__ ln_g, const float* __restrict__ ln_b,
                 const float* __restrict__ Wg2,  const float* __restrict__ bg2,
                 const float* __restrict__ Wq,   const float* __restrict__ bq,
                 const float* __restrict__ Wk,   const float* __restrict__ Wv)
{
    const int tid = threadIdx.x;
    const int lane = tid & 31, wid = tid >> 5;

    if (blockIdx.x >= B) {
        // ---------------- table block (uses only 256 threads) ----------------
        if (tid >= 256) return;
        const int tblk = blockIdx.x - B;         // 0..127
        const int l8 = tid & 31, w8 = tid >> 5;  // 8 warps
        __shared__ float ls[HW];
        __shared__ float rmx[8], rmn[8];

        float mx = -1e30f, mn = 1e30f;
        #pragma unroll
        for (int j = tid; j < HW; j += 256) {
            const float v = l[j];
            ls[j] = v;
            mx = fmaxf(mx, v);
            mn = fminf(mn, v);
        }
        #pragma unroll
        for (int o = 16; o; o >>= 1) {
            mx = fmaxf(mx, __shfl_xor_sync(0xffffffffu, mx, o));
            mn = fminf(mn, __shfl_xor_sync(0xffffffffu, mn, o));
        }
        if (l8 == 0) { rmx[w8] = mx; rmn[w8] = mn; }
        __syncthreads();
        float lmax = rmx[0], lmin = rmn[0];
        #pragma unroll
        for (int k = 1; k < 8; k++) {
            lmax = fmaxf(lmax, rmx[k]);
            lmin = fminf(lmin, rmn[k]);
        }

        const int e0 = tblk * 16 + 2 * w8;
        const float u0 = (e0 + 0.5f) * (PI_F / M_TAB) - 0.5f * PI_F;
        const float u1 = (e0 + 1.5f) * (PI_F / M_TAB) - 0.5f * PI_F;
        const float al0 = ALPHA * tanf(u0) * 1.4426950408889634f;
        const float al1 = ALPHA * tanf(u1) * 1.4426950408889634f;
        const float m20 = (al0 > 0.0f) ? al0 * lmax : al0 * lmin;
        const float m21 = (al1 > 0.0f) ? al1 * lmax : al1 * lmin;
        float S0 = 0.0f, T0 = 0.0f, S1 = 0.0f, T1 = 0.0f;
        #pragma unroll 8
        for (int j = l8; j < HW; j += 32) {
            const float lj = ls[j];
            const float ev0 = ex2f(fmaf(al0, lj, -m20));
            const float ev1 = ex2f(fmaf(al1, lj, -m21));
            S0 += ev0;
            T0 = fmaf(lj, ev0, T0);
            S1 += ev1;
            T1 = fmaf(lj, ev1, T1);
        }
        S0 = warp_sum(S0);
        T0 = warp_sum(T0);
        S1 = warp_sum(S1);
        T1 = warp_sum(T1);
        if (l8 == 0) {
            g_tab[e0]     = T0 / S0;
            g_tab[e0 + 1] = T1 / S1;
        }
        return;
    }

    // ---------------- prep block (one batch, 512 threads) ----------------
    const int b = blockIdx.x;

    __shared__ float t_s[C2];
    __shared__ float gv_s[C];
    __shared__ float part_f[2048];               // 8 k-chunks x 256 c
    __shared__ float kg_s[DK];
    __shared__ float red[16];
    __shared__ float bcast[2];

    // ---- combine p1 partials (fixed order: deterministic) ----
    float v = bg1[tid];
    #pragma unroll
    for (int ct = 0; ct < 8; ct++) v += g_tp[ct * (B * C2) + b * C2 + tid];

    // ---- LayerNorm + exact GELU ----
    float s1 = warp_sum(v);
    if (lane == 0) red[wid] = s1;
    __syncthreads();
    if (wid == 0) {
        float r = (lane < 16) ? red[lane] : 0.0f;
        r = warp_sum(r);
        if (lane == 0) bcast[0] = r * (1.0f / C2);
    }
    __syncthreads();
    const float mu = bcast[0];
    const float d = v - mu;
    float s2 = warp_sum(d * d);
    if (lane == 0) red[wid] = s2;
    __syncthreads();
    if (wid == 0) {
        float r = (lane < 16) ? red[lane] : 0.0f;
        r = warp_sum(r);
        if (lane == 0) bcast[1] = rsqrtf(r * (1.0f / C2) + 1e-5f);
    }
    __syncthreads();
    {
        float x = d * bcast[1] * ln_g[tid] + ln_b[tid];
        t_s[tid] = 0.5f * x * (1.0f + erff(x * 0.7071067811865476f));
    }
    __syncthreads();

    // ---- GvT[c] = sum_k t[k] * Wg2[k*C + c] + bg2[c] : 2-acc ILP ----
    {
        const int q = tid & 63;       // c-group: c = 4q .. 4q+3
        const int h = tid >> 6;       // k-chunk: k in [h*64, h*64+64)
        const float4* W4 = (const float4*)Wg2;   // [512][64] float4
        float4 a0 = make_float4(0.f, 0.f, 0.f, 0.f);
        float4 a1 = a0;
        const int k0 = h * 64;
        #pragma unroll 16
        for (int kk = 0; kk < 32; kk++) {
            const float t0 = t_s[k0 + kk];
            const float t1 = t_s[k0 + 32 + kk];
            const float4 w0 = W4[(k0 + kk) * 64 + q];
            const float4 w1 = W4[(k0 + 32 + kk) * 64 + q];
            a0.x = fmaf(t0, w0.x, a0.x); a0.y = fmaf(t0, w0.y, a0.y);
            a0.z = fmaf(t0, w0.z, a0.z); a0.w = fmaf(t0, w0.w, a0.w);
            a1.x = fmaf(t1, w1.x, a1.x); a1.y = fmaf(t1, w1.y, a1.y);
            a1.z = fmaf(t1, w1.z, a1.z); a1.w = fmaf(t1, w1.w, a1.w);
        }
        part_f[h * 256 + 4 * q + 0] = a0.x + a1.x;
        part_f[h * 256 + 4 * q + 1] = a0.y + a1.y;
        part_f[h * 256 + 4 * q + 2] = a0.z + a1.z;
        part_f[h * 256 + 4 * q + 3] = a0.w + a1.w;
    }
    __syncthreads();
    if (tid < C) {
        float g = bg2[tid];
        #pragma unroll
        for (int h = 0; h < 8; h++) g += part_f[h * 256 + tid];
        gv_s[tid] = g;
    }
    __syncthreads();

    // ---- vg[c] = Wv[c,:] . gv : 16 outputs/warp, pipelined reductions ----
    {
        const float4* Wv4 = (const float4*)Wv;        // [256][64] float4
        const float4* gv4 = (const float4*)gv_s;
        const float4 gA = gv4[lane];
        const float4 gB = gv4[32 + lane];
        #pragma unroll
        for (int g = 0; g < 2; g++) {
            float part[8];
            #pragma unroll
            for (int oo = 0; oo < 8; oo++) {
                const int c = wid * 16 + g * 8 + oo;
                const float4 wA = Wv4[c * 64 + lane];
                const float4 wB = Wv4[c * 64 + 32 + lane];
                part[oo] = wA.x * gA.x + wA.y * gA.y + wA.z * gA.z + wA.w * gA.w
                         + wB.x * gB.x + wB.y * gB.y + wB.z * gB.z + wB.w * gB.w;
            }
            #pragma unroll
            for (int oo = 0; oo < 8; oo++) part[oo] = warp_sum(part[oo]);
            if (lane == 0) {
                #pragma unroll
                for (int oo = 0; oo < 8; oo++)
                    g_vg[b * C + wid * 16 + g * 8 + oo] = part[oo];
            }
        }
        // ---- kg[d] = Wk[d,:] . gv : 2 outputs/warp ----
        const float4* Wk4 = (const float4*)Wk;        // [32][64] float4
        {
            float pk[2];
            #pragma unroll
            for (int oo = 0; oo < 2; oo++) {
                const int dd = wid * 2 + oo;
                const float4 wA = Wk4[dd * 64 + lane];
                const float4 wB = Wk4[dd * 64 + 32 + lane];
                pk[oo] = wA.x * gA.x + wA.y * gA.y + wA.z * gA.z + wA.w * gA.w
                       + wB.x * gB.x + wB.y * gB.y + wB.z * gB.z + wB.w * gB.w;
            }
            #pragma unroll
            for (int oo = 0; oo < 2; oo++) pk[oo] = warp_sum(pk[oo]);
            if (lane == 0) {
                kg_s[wid * 2 + 0] = pk[0];
                kg_s[wid * 2 + 1] = pk[1];
            }
        }
    }
    __syncthreads();

    // ---- wqk[c] = sum_d kg[d] * Wq[d*C + c];  qb = bq . kg ----
    if (tid < C) {
        float acc = 0.0f;
        #pragma unroll
        for (int dd = 0; dd < DK; dd++) acc = fmaf(kg_s[dd], Wq[dd * C + tid], acc);
        g_wqk[b * C + tid] = acc;
    }
    if (wid == 0) {
        float p = bq[lane] * kg_s[lane];
        p = warp_sum(p);
        if (lane == 0) g_qb[b] = p;
    }
}

// ---------------------------------------------------------------------------
// Attention: pure memory stream. block = 256 thr; warp s owns channels
// [32s, 32s+32) for the block's 32 pixels (lane = pixel). img read ONCE into
// registers; s(a) via 4-tap Catmull-Rom from the smem-cached table.
// grid (72, 8), occ 4.
// ---------------------------------------------------------------------------
__global__ __launch_bounds__(256, 4)
void attn_kernel(const float* __restrict__ img,
                 const float* __restrict__ bv,
                 const float* __restrict__ gamma_p,
                 float* __restrict__ out)
{
    const int b = blockIdx.y;
    const int tid = threadIdx.x;
    const int p = tid & 31;      // pixel within block (lane)
    const int s = tid >> 5;      // channel-split 0..7 (warp)
    const int i = blockIdx.x * 32 + p;
    const int c0 = s * 32;

    __shared__ float tab_s[M_TAB];
    __shared__ float wq[C];
    __shared__ float vgs[C];
    __shared__ float bvs[C];
    __shared__ float partA[256];

    // front-batch img loads (32 contiguous channels per thread) into registers
    float im[32];
    const float* xb = img + (size_t)b * C * HW + (size_t)c0 * HW + i;
    #pragma unroll
    for (int cc = 0; cc < 32; cc++) im[cc] = xb[(size_t)cc * HW];

    const float gm = *gamma_p;
    const float qb = g_qb[b];

    // smem fills overlap the in-flight img loads
    #pragma unroll
    for (int k = tid; k < M_TAB; k += 256) tab_s[k] = g_tab[k];
    wq[tid]  = g_wqk[b * C + tid];
    vgs[tid] = g_vg[b * C + tid];
    bvs[tid] = bv[tid];
    __syncthreads();

    // partial dot over this thread's 32 channels
    float a = 0.0f;
    #pragma unroll
    for (int cc = 0; cc < 32; cc++) a = fmaf(wq[c0 + cc], im[cc], a);
    partA[tid] = a;
    __syncthreads();
    float af = qb;
    #pragma unroll
    for (int k = 0; k < 8; k++) af += partA[k * 32 + p];

    // s(af) via table: u = atan(af/ALPHA); cubic Catmull-Rom in u-grid
    const float u = atanf(af * (1.0f / ALPHA));
    const float idx = u * (M_TAB / PI_F) + (M_TAB * 0.5f - 0.5f);
    const float fi = floorf(idx);
    const float t = idx - fi;
    const int i1 = (int)fi;
    const int j0 = max(i1 - 1, 0);
    const int j1 = min(max(i1, 0), M_TAB - 1);
    const int j2 = min(i1 + 1, M_TAB - 1);
    const int j3 = min(i1 + 2, M_TAB - 1);
    const float p0 = tab_s[j0], p1v = tab_s[j1], p2 = tab_s[j2], p3 = tab_s[j3];
    const float sv = p1v + 0.5f * t * (p2 - p0
                   + t * (2.0f * p0 - 5.0f * p1v + 4.0f * p2 - p3
                   + t * (3.0f * (p1v - p2) + p3 - p0)));

    // out[b,c,i] = img + gamma * (vg[c]*sv + bv[c]) using register-cached img
    float* ob = out + (size_t)b * C * HW + (size_t)c0 * HW + i;
    #pragma unroll
    for (int cc = 0; cc < 32; cc++) {
        ob[(size_t)cc * HW] = fmaf(gm, fmaf(vgs[c0 + cc], sv, bvs[c0 + cc]), im[cc]);
    }
}

extern "C" void kernel_launch(void* const* d_in, const int* in_sizes, int n_in,
                              void* d_out, int out_size)
{
    const float* img   = (const float*)d_in[0];
    const float* text  = (const float*)d_in[1];
    const float* l     = (const float*)d_in[2];
    const float* Wg1   = (const float*)d_in[3];
    const float* bg1   = (const float*)d_in[4];
    const float* ln_g  = (const float*)d_in[5];
    const float* ln_b  = (const float*)d_in[6];
    const float* Wg2   = (const float*)d_in[7];
    const float* bg2   = (const float*)d_in[8];
    const float* Wq    = (const float*)d_in[9];
    const float* bq    = (const float*)d_in[10];
    const float* Wk    = (const float*)d_in[11];
    // d_in[12] = bk : cancels in softmax, unused
    const float* Wv    = (const float*)d_in[13];
    const float* bv    = (const float*)d_in[14];
    const float* gamma = (const float*)d_in[15];
    float* out = (float*)d_out;

    p1_kernel<<<128, 256>>>(text, Wg1);
    prep_kernel<<<B + NTABBLK, 512>>>(l, bg1, ln_g, ln_b, Wg2, bg2,
                                      Wq, bq, Wk, Wv);
    dim3 grid(HW / 32, B);
    attn_kernel<<<grid, 256>>>(img, bv, gamma, out);
}